// round 8
// baseline (speedup 1.0000x reference)
#include <cuda_runtime.h>
#include <cuda_bf16.h>
#include <cstdint>

// Problem constants
#define KW 7
#define CC 256
#define BB 4
#define HWN 1024          // 32*32
#define PW2 40            // padded smem row stride (floats)
#define PHW2 (38 * PW2)   // 1520 floats per plane

// Scratch (device globals)
__device__ float g_q[BB * CC * HWN];
__device__ float g_k[BB * CC * HWN];
__device__ float g_v[BB * CC * HWN];
__device__ __nv_bfloat16 g_Whi[3 * 256 * 256];
__device__ __nv_bfloat16 g_Wlo[3 * 256 * 256];
__device__ __nv_bfloat16 g_Xhi[BB * 256 * 1024];
__device__ __nv_bfloat16 g_Xlo[BB * 256 * 1024];

// ---------------------------------------------------------------------------
// helpers
// ---------------------------------------------------------------------------
__device__ __forceinline__ uint32_t smem_u32(const void* p) {
    uint32_t a;
    asm("{ .reg .u64 t; cvta.to.shared.u64 t, %1; cvt.u32.u64 %0, t; }" : "=r"(a) : "l"(p));
    return a;
}
__device__ __forceinline__ void ldsm_x4(uint32_t r[4], uint32_t addr) {
    asm volatile("ldmatrix.sync.aligned.m8n8.x4.shared.b16 {%0,%1,%2,%3}, [%4];"
                 : "=r"(r[0]), "=r"(r[1]), "=r"(r[2]), "=r"(r[3]) : "r"(addr));
}
__device__ __forceinline__ void ldsm_x4_t(uint32_t r[4], uint32_t addr) {
    asm volatile("ldmatrix.sync.aligned.m8n8.x4.trans.shared.b16 {%0,%1,%2,%3}, [%4];"
                 : "=r"(r[0]), "=r"(r[1]), "=r"(r[2]), "=r"(r[3]) : "r"(addr));
}
__device__ __forceinline__ void mma_bf16(float c[4], const uint32_t a[4],
                                         uint32_t b0, uint32_t b1) {
    asm volatile(
        "mma.sync.aligned.m16n8k16.row.col.f32.bf16.bf16.f32 "
        "{%0,%1,%2,%3}, {%4,%5,%6,%7}, {%8,%9}, {%0,%1,%2,%3};"
        : "+f"(c[0]), "+f"(c[1]), "+f"(c[2]), "+f"(c[3])
        : "r"(a[0]), "r"(a[1]), "r"(a[2]), "r"(a[3]), "r"(b0), "r"(b1));
}
__device__ __forceinline__ void split_bf(float a, __nv_bfloat16& h, __nv_bfloat16& l) {
    h = __float2bfloat16(a);
    l = __float2bfloat16(a - __bfloat162float(h));
}
__device__ __forceinline__ uint32_t pack2(__nv_bfloat16 a, __nv_bfloat16 b) {
    __nv_bfloat162 t; t.x = a; t.y = b;
    return *(uint32_t*)&t;
}
#define CP_ASYNC16(dst, src) \
    asm volatile("cp.async.cg.shared.global [%0], [%1], 16;" :: "r"(dst), "l"(src))
#define CP_COMMIT() asm volatile("cp.async.commit_group;" ::: "memory")
#define CP_WAIT(N)  asm volatile("cp.async.wait_group %0;" :: "n"(N) : "memory")

// f32x2 packed math (sm_100 base ISA)
typedef unsigned long long u64t;
__device__ __forceinline__ u64t pkf2(float a, float b) {
    u64t r; asm("mov.b64 %0, {%1, %2};" : "=l"(r) : "f"(a), "f"(b)); return r;
}
__device__ __forceinline__ void upkf2(float& a, float& b, u64t r) {
    asm("mov.b64 {%0, %1}, %2;" : "=f"(a), "=f"(b) : "l"(r));
}
__device__ __forceinline__ u64t fma2(u64t a, u64t b, u64t c) {
    u64t d; asm("fma.rn.f32x2 %0, %1, %2, %3;" : "=l"(d) : "l"(a), "l"(b), "l"(c)); return d;
}
__device__ __forceinline__ u64t add2(u64t a, u64t b) {
    u64t d; asm("add.rn.f32x2 %0, %1, %2;" : "=l"(d) : "l"(a), "l"(b)); return d;
}
__device__ __forceinline__ u64t mul2(u64t a, u64t b) {
    u64t d; asm("mul.rn.f32x2 %0, %1, %2;" : "=l"(d) : "l"(a), "l"(b)); return d;
}
__device__ __forceinline__ float ex2f(float x) {
    float y;
    asm("ex2.approx.ftz.f32 %0, %1;" : "=f"(y) : "f"(x));
    return y;
}
__device__ __forceinline__ u64t ex2_2(u64t t) {
    float lo, hi; upkf2(lo, hi, t);
    return pkf2(ex2f(lo), ex2f(hi));
}

// ---------------------------------------------------------------------------
// Pre-convert: grid 1216 x 256, 1 float4/thread.
// ---------------------------------------------------------------------------
__global__ __launch_bounds__(256) void convert_kernel(
    const float* __restrict__ x,
    const float* __restrict__ wq,
    const float* __restrict__ wk,
    const float* __restrict__ wv)
{
    const int tid = threadIdx.x;
    __nv_bfloat16 h0, l0, h1, l1, h2, l2, h3, l3;
    if (blockIdx.x < 1024) {
        int i4 = blockIdx.x * 256 + tid;
        float4 v = ((const float4*)x)[i4];
        split_bf(v.x, h0, l0); split_bf(v.y, h1, l1);
        split_bf(v.z, h2, l2); split_bf(v.w, h3, l3);
        int base = i4 * 4;
        *(uint2*)&g_Xhi[base] = make_uint2(pack2(h0, h1), pack2(h2, h3));
        *(uint2*)&g_Xlo[base] = make_uint2(pack2(l0, l1), pack2(l2, l3));
    } else {
        int i4 = (blockIdx.x - 1024) * 256 + tid;
        int mat = i4 >> 14;
        int off4 = i4 & 16383;
        const float* Wp = (mat == 0) ? wq : (mat == 1) ? wk : wv;
        float4 v = ((const float4*)Wp)[off4];
        split_bf(v.x, h0, l0); split_bf(v.y, h1, l1);
        split_bf(v.z, h2, l2); split_bf(v.w, h3, l3);
        int base = i4 * 4;
        *(uint2*)&g_Whi[base] = make_uint2(pack2(h0, h1), pack2(h2, h3));
        *(uint2*)&g_Wlo[base] = make_uint2(pack2(l0, l1), pack2(l2, l3));
    }
}

// ---------------------------------------------------------------------------
// bf16 split-precision QKV GEMM, cp.async 2-stage pipeline (3 CTAs/SM).
// ---------------------------------------------------------------------------
#define SKA 48
#define SKB 136
#define OFF_AL 6144
#define OFF_BH 12288
#define OFF_BL 20992
#define STG_BYTES 29696
#define SMEM_TOTAL (2 * STG_BYTES)

__global__ __launch_bounds__(256, 3) void qkv_mma_kernel()
{
    extern __shared__ char sm[];
    const uint32_t sm_base = smem_u32(sm);

    const int tid  = threadIdx.x;
    const int wid  = tid >> 5;
    const int lane = tid & 31;
    const int wm   = wid >> 2;
    const int wn   = wid & 3;
    const int b    = blockIdx.y;
    const int m0g  = (blockIdx.x >> 3) * 64;
    const int n0   = (blockIdx.x & 7) * 128;

    const int ar  = tid >> 2;
    const int ac  = (tid & 3) << 3;
    const int br  = tid >> 4;
    const int bc  = (tid & 15) << 3;

    const __nv_bfloat16* AgH = g_Whi + (size_t)(m0g + ar) * 256 + ac;
    const __nv_bfloat16* AgL = g_Wlo + (size_t)(m0g + ar) * 256 + ac;
    const __nv_bfloat16* BgH = g_Xhi + ((size_t)(b * 256 + br)) * 1024 + n0 + bc;
    const __nv_bfloat16* BgL = g_Xlo + ((size_t)(b * 256 + br)) * 1024 + n0 + bc;

    const uint32_t adst = (uint32_t)(ar * SKA + ac) * 2u;
    const uint32_t bdst = (uint32_t)(br * SKB + bc) * 2u;

    auto issue = [&](int ch) {
        const uint32_t stb = sm_base + (ch & 1) * STG_BYTES;
        const int k0 = ch * 32;
        CP_ASYNC16(stb + adst,          AgH + k0);
        CP_ASYNC16(stb + OFF_AL + adst, AgL + k0);
        #pragma unroll
        for (int t = 0; t < 2; t++) {
            uint32_t d = bdst + (uint32_t)(t * 16 * SKB) * 2u;
            CP_ASYNC16(stb + OFF_BH + d, BgH + (size_t)(k0 + t * 16) * 1024);
            CP_ASYNC16(stb + OFF_BL + d, BgL + (size_t)(k0 + t * 16) * 1024);
        }
        CP_COMMIT();
    };

    issue(0);
    issue(1);

    float acc[2][4][4];
    #pragma unroll
    for (int i = 0; i < 2; i++)
        #pragma unroll
        for (int j = 0; j < 4; j++)
            #pragma unroll
            for (int r = 0; r < 4; r++) acc[i][j][r] = 0.f;

    #pragma unroll
    for (int ch = 0; ch < 8; ch++) {
        if (ch < 7) { CP_WAIT(1); } else { CP_WAIT(0); }
        __syncthreads();

        const uint32_t stb = sm_base + (ch & 1) * STG_BYTES;
        #pragma unroll
        for (int ks = 0; ks < 2; ks++) {
            const int kk = ks * 16;
            uint32_t afh[2][4], afl[2][4];
            #pragma unroll
            for (int mt = 0; mt < 2; mt++) {
                uint32_t aoff = (uint32_t)((wm * 32 + mt * 16 + (lane & 15)) * SKA
                                           + kk + ((lane >> 4) << 3)) * 2u;
                ldsm_x4(afh[mt], stb + aoff);
                ldsm_x4(afl[mt], stb + OFF_AL + aoff);
            }
            uint32_t bfh[4][2], bfl[4][2];
            #pragma unroll
            for (int p = 0; p < 2; p++) {
                uint32_t boff = (uint32_t)((kk + (lane & 15)) * SKB
                                           + wn * 32 + p * 16 + ((lane >> 4) << 3)) * 2u;
                uint32_t r[4];
                ldsm_x4_t(r, stb + OFF_BH + boff);
                bfh[p * 2][0] = r[0]; bfh[p * 2][1] = r[1];
                bfh[p * 2 + 1][0] = r[2]; bfh[p * 2 + 1][1] = r[3];
                ldsm_x4_t(r, stb + OFF_BL + boff);
                bfl[p * 2][0] = r[0]; bfl[p * 2][1] = r[1];
                bfl[p * 2 + 1][0] = r[2]; bfl[p * 2 + 1][1] = r[3];
            }
            #pragma unroll
            for (int mt = 0; mt < 2; mt++)
                #pragma unroll
                for (int nt = 0; nt < 4; nt++) {
                    mma_bf16(acc[mt][nt], afh[mt], bfh[nt][0], bfh[nt][1]);
                    mma_bf16(acc[mt][nt], afh[mt], bfl[nt][0], bfl[nt][1]);
                    mma_bf16(acc[mt][nt], afl[mt], bfh[nt][0], bfh[nt][1]);
                }
        }
        __syncthreads();
        if (ch + 2 < 8) issue(ch + 2);
    }

    const int mat = m0g >> 8;
    float* outp = (mat == 0) ? g_q : (mat == 1) ? g_k : g_v;
    const int orow = (m0g & 255) + wm * 32;
    #pragma unroll
    for (int mt = 0; mt < 2; mt++) {
        int o = orow + mt * 16 + (lane >> 2);
        #pragma unroll
        for (int nt = 0; nt < 4; nt++) {
            int n = n0 + wn * 32 + nt * 8 + ((lane & 3) << 1);
            float* og = outp + ((size_t)(b * CC + o)) * HWN + n;
            *(float2*)og = make_float2(acc[mt][nt][0], acc[mt][nt][1]);
            *(float2*)(og + 8 * HWN) = make_float2(acc[mt][nt][2], acc[mt][nt][3]);
        }
    }
}

// ---------------------------------------------------------------------------
// Windowed softmax attention with packed f32x2 math.
// 512 blocks x 2 channels, cp.async double-buffered.
// ---------------------------------------------------------------------------
__global__ __launch_bounds__(256, 4) void attn_kernel(
    const float* __restrict__ rel_h,
    const float* __restrict__ rel_w,
    float* __restrict__ out)
{
    __shared__ float ks[2][PHW2];
    __shared__ float vs[2][PHW2];
    __shared__ float brow_s[2][8];

    const int tid = threadIdx.x;
    const int p0 = tid * 4;
    const int h  = p0 >> 5;
    const int w0 = p0 & 31;
    const int pi0 = (h + 3) * PW2 + (w0 + 4);

    for (int i = tid; i < PHW2; i += 256) {
        ks[0][i] = 0.f; ks[1][i] = 0.f;
        vs[0][i] = 0.f; vs[1][i] = 0.f;
    }

    const int j0 = blockIdx.x * 2;
    const int b0 = j0 >> 8,       c0 = j0 & 255;
    const int b1 = (j0 + 1) >> 8, c1 = (j0 + 1) & 255;
    const bool hsel0 = (c0 < CC / 2);
    const bool hsel1 = (c1 < CC / 2);

    if (tid < KW) {
        brow_s[0][tid] = hsel0 ? rel_h[c0 * KW + tid] : rel_w[(c0 - CC / 2) * KW + tid];
        brow_s[1][tid] = hsel1 ? rel_h[c1 * KW + tid] : rel_w[(c1 - CC / 2) * KW + tid];
    }

    const uint32_t ksa0 = smem_u32(&ks[0][0]) + pi0 * 4;
    const uint32_t vsa0 = smem_u32(&vs[0][0]) + pi0 * 4;
    const uint32_t ksa1 = smem_u32(&ks[1][0]) + pi0 * 4;
    const uint32_t vsa1 = smem_u32(&vs[1][0]) + pi0 * 4;

    CP_ASYNC16(ksa0, g_k + ((size_t)(b0 * CC + c0)) * HWN + p0);
    CP_ASYNC16(vsa0, g_v + ((size_t)(b0 * CC + c0)) * HWN + p0);
    CP_COMMIT();
    CP_ASYNC16(ksa1, g_k + ((size_t)(b1 * CC + c1)) * HWN + p0);
    CP_ASYNC16(vsa1, g_v + ((size_t)(b1 * CC + c1)) * HWN + p0);
    CP_COMMIT();

    float4 qv0 = *(const float4*)(g_q + ((size_t)(b0 * CC + c0)) * HWN + p0);
    float4 qv1 = *(const float4*)(g_q + ((size_t)(b1 * CC + c1)) * HWN + p0);

    const float LOG2E = 1.4426950408889634f;

    #pragma unroll
    for (int rep = 0; rep < 2; rep++) {
        if (rep == 0) { CP_WAIT(1); } else { CP_WAIT(0); }
        __syncthreads();

        const float4 qv = (rep == 0) ? qv0 : qv1;
        const bool hsel = (rep == 0) ? hsel0 : hsel1;
        const float* ksp = ks[rep];
        const float* vsp = vs[rep];
        const float* bw  = brow_s[rep];

        const float q0 = qv.x * LOG2E, q1 = qv.y * LOG2E;
        const float q2v = qv.z * LOG2E, q3 = qv.w * LOG2E;
        const u64t q2p01 = pkf2(q0, q1);
        const u64t q2p23 = pkf2(q2v, q3);

        u64t sum01 = pkf2(0.f, 0.f), sum23 = sum01;
        u64t acc01 = sum01, acc23 = sum01;

        if (hsel) {
            #pragma unroll
            for (int u = 0; u < KW; u++) {
                const int rbase = (h + u) * PW2 + w0 + 1;
                float kr[10], vr[10];
                #pragma unroll
                for (int i = 0; i < 10; i++) { kr[i] = ksp[rbase + i]; vr[i] = vsp[rbase + i]; }
                const float bu = bw[u];
                const u64t bup = pkf2(bu, bu);
                const u64t qb01 = mul2(q2p01, bup);
                const u64t qb23 = mul2(q2p23, bup);
                #pragma unroll
                for (int v = 0; v < KW; v++) {
                    u64t kp01 = pkf2(kr[v],     kr[v + 1]);
                    u64t kp23 = pkf2(kr[v + 2], kr[v + 3]);
                    u64t e01 = ex2_2(fma2(q2p01, kp01, qb01));
                    u64t e23 = ex2_2(fma2(q2p23, kp23, qb23));
                    sum01 = add2(sum01, e01);
                    sum23 = add2(sum23, e23);
                    u64t vp01 = pkf2(vr[v],     vr[v + 1]);
                    u64t vp23 = pkf2(vr[v + 2], vr[v + 3]);
                    acc01 = fma2(e01, vp01, acc01);
                    acc23 = fma2(e23, vp23, acc23);
                }
            }
        } else {
            #pragma unroll
            for (int u = 0; u < KW; u++) {
                const int rbase = (h + u) * PW2 + w0 + 1;
                float kr[10], vr[10];
                #pragma unroll
                for (int i = 0; i < 10; i++) { kr[i] = ksp[rbase + i]; vr[i] = vsp[rbase + i]; }
                #pragma unroll
                for (int v = 0; v < KW; v++) {
                    const float bv = bw[v];
                    const u64t bvp = pkf2(bv, bv);
                    const u64t qb01 = mul2(q2p01, bvp);
                    const u64t qb23 = mul2(q2p23, bvp);
                    u64t kp01 = pkf2(kr[v],     kr[v + 1]);
                    u64t kp23 = pkf2(kr[v + 2], kr[v + 3]);
                    u64t e01 = ex2_2(fma2(q2p01, kp01, qb01));
                    u64t e23 = ex2_2(fma2(q2p23, kp23, qb23));
                    sum01 = add2(sum01, e01);
                    sum23 = add2(sum23, e23);
                    u64t vp01 = pkf2(vr[v],     vr[v + 1]);
                    u64t vp23 = pkf2(vr[v + 2], vr[v + 3]);
                    acc01 = fma2(e01, vp01, acc01);
                    acc23 = fma2(e23, vp23, acc23);
                }
            }
        }

        float s0, s1, s2, s3, a0, a1, a2, a3;
        upkf2(s0, s1, sum01); upkf2(s2, s3, sum23);
        upkf2(a0, a1, acc01); upkf2(a2, a3, acc23);

        float* og = out + ((size_t)(j0 + rep)) * HWN + p0;
        float4 r;
        r.x = __fdividef(a0, s0);
        r.y = __fdividef(a1, s1);
        r.z = __fdividef(a2, s2);
        r.w = __fdividef(a3, s3);
        *(float4*)og = r;
    }
}

// ---------------------------------------------------------------------------
extern "C" void kernel_launch(void* const* d_in, const int* in_sizes, int n_in,
                              void* d_out, int out_size)
{
    const float* x     = (const float*)d_in[0];
    const float* wq    = (const float*)d_in[1];
    const float* wk    = (const float*)d_in[2];
    const float* wv    = (const float*)d_in[3];
    const float* rel_h = (const float*)d_in[4];
    const float* rel_w = (const float*)d_in[5];
    float* out = (float*)d_out;

    cudaFuncSetAttribute(qkv_mma_kernel, cudaFuncAttributeMaxDynamicSharedMemorySize,
                         SMEM_TOTAL);

    convert_kernel<<<1216, 256>>>(x, wq, wk, wv);

    dim3 gg(96, BB);
    qkv_mma_kernel<<<gg, 256, SMEM_TOTAL>>>();

    attn_kernel<<<512, 256>>>(rel_h, rel_w, out);
}

// round 10
// speedup vs baseline: 1.0532x; 1.0532x over previous
#include <cuda_runtime.h>
#include <cuda_bf16.h>
#include <cstdint>

// Problem constants
#define KW 7
#define CC 256
#define BB 4
#define HWN 1024          // 32*32
#define PW2 40            // padded smem row stride (floats)
#define PHW2 (38 * PW2)   // 1520 floats per plane

// Scratch (device globals)
__device__ float g_q[BB * CC * HWN];
__device__ float g_k[BB * CC * HWN];
__device__ float g_v[BB * CC * HWN];
__device__ __nv_bfloat16 g_Whi[3 * 256 * 256];
__device__ __nv_bfloat16 g_Wlo[3 * 256 * 256];
__device__ __nv_bfloat16 g_Xhi[BB * 256 * 1024];
__device__ __nv_bfloat16 g_Xlo[BB * 256 * 1024];
__device__ int g_attn_ctr;

// ---------------------------------------------------------------------------
// helpers
// ---------------------------------------------------------------------------
__device__ __forceinline__ uint32_t smem_u32(const void* p) {
    uint32_t a;
    asm("{ .reg .u64 t; cvta.to.shared.u64 t, %1; cvt.u32.u64 %0, t; }" : "=r"(a) : "l"(p));
    return a;
}
__device__ __forceinline__ void ldsm_x4(uint32_t r[4], uint32_t addr) {
    asm volatile("ldmatrix.sync.aligned.m8n8.x4.shared.b16 {%0,%1,%2,%3}, [%4];"
                 : "=r"(r[0]), "=r"(r[1]), "=r"(r[2]), "=r"(r[3]) : "r"(addr));
}
__device__ __forceinline__ void ldsm_x4_t(uint32_t r[4], uint32_t addr) {
    asm volatile("ldmatrix.sync.aligned.m8n8.x4.trans.shared.b16 {%0,%1,%2,%3}, [%4];"
                 : "=r"(r[0]), "=r"(r[1]), "=r"(r[2]), "=r"(r[3]) : "r"(addr));
}
__device__ __forceinline__ void mma_bf16(float c[4], const uint32_t a[4],
                                         uint32_t b0, uint32_t b1) {
    asm volatile(
        "mma.sync.aligned.m16n8k16.row.col.f32.bf16.bf16.f32 "
        "{%0,%1,%2,%3}, {%4,%5,%6,%7}, {%8,%9}, {%0,%1,%2,%3};"
        : "+f"(c[0]), "+f"(c[1]), "+f"(c[2]), "+f"(c[3])
        : "r"(a[0]), "r"(a[1]), "r"(a[2]), "r"(a[3]), "r"(b0), "r"(b1));
}
__device__ __forceinline__ void split_bf(float a, __nv_bfloat16& h, __nv_bfloat16& l) {
    h = __float2bfloat16(a);
    l = __float2bfloat16(a - __bfloat162float(h));
}
__device__ __forceinline__ uint32_t pack2(__nv_bfloat16 a, __nv_bfloat16 b) {
    __nv_bfloat162 t; t.x = a; t.y = b;
    return *(uint32_t*)&t;
}
#define CP_ASYNC16(dst, src) \
    asm volatile("cp.async.cg.shared.global [%0], [%1], 16;" :: "r"(dst), "l"(src))
#define CP_COMMIT() asm volatile("cp.async.commit_group;" ::: "memory")
#define CP_WAIT(N)  asm volatile("cp.async.wait_group %0;" :: "n"(N) : "memory")

__device__ __forceinline__ float ex2f(float x) {
    float y;
    asm("ex2.approx.ftz.f32 %0, %1;" : "=f"(y) : "f"(x));
    return y;
}

// ---------------------------------------------------------------------------
// Pre-convert: grid 1216 x 256, 1 float4/thread. Also resets the attn counter.
// ---------------------------------------------------------------------------
__global__ __launch_bounds__(256) void convert_kernel(
    const float* __restrict__ x,
    const float* __restrict__ wq,
    const float* __restrict__ wk,
    const float* __restrict__ wv)
{
    const int tid = threadIdx.x;
    if (blockIdx.x == 0 && tid == 0) g_attn_ctr = 0;

    __nv_bfloat16 h0, l0, h1, l1, h2, l2, h3, l3;
    if (blockIdx.x < 1024) {
        int i4 = blockIdx.x * 256 + tid;
        float4 v = ((const float4*)x)[i4];
        split_bf(v.x, h0, l0); split_bf(v.y, h1, l1);
        split_bf(v.z, h2, l2); split_bf(v.w, h3, l3);
        int base = i4 * 4;
        *(uint2*)&g_Xhi[base] = make_uint2(pack2(h0, h1), pack2(h2, h3));
        *(uint2*)&g_Xlo[base] = make_uint2(pack2(l0, l1), pack2(l2, l3));
    } else {
        int i4 = (blockIdx.x - 1024) * 256 + tid;
        int mat = i4 >> 14;
        int off4 = i4 & 16383;
        const float* Wp = (mat == 0) ? wq : (mat == 1) ? wk : wv;
        float4 v = ((const float4*)Wp)[off4];
        split_bf(v.x, h0, l0); split_bf(v.y, h1, l1);
        split_bf(v.z, h2, l2); split_bf(v.w, h3, l3);
        int base = i4 * 4;
        *(uint2*)&g_Whi[base] = make_uint2(pack2(h0, h1), pack2(h2, h3));
        *(uint2*)&g_Wlo[base] = make_uint2(pack2(l0, l1), pack2(l2, l3));
    }
}

// ---------------------------------------------------------------------------
// bf16 split-precision QKV GEMM, cp.async 2-stage pipeline (3 CTAs/SM).
// 64x128 tile, BK=32, 8 warps. grid: x = 96, y = batch(4).
// ---------------------------------------------------------------------------
#define SKA 48
#define SKB 136
#define OFF_AL 6144
#define OFF_BH 12288
#define OFF_BL 20992
#define STG_BYTES 29696
#define SMEM_TOTAL (2 * STG_BYTES)

__global__ __launch_bounds__(256, 3) void qkv_mma_kernel()
{
    extern __shared__ char sm[];
    const uint32_t sm_base = smem_u32(sm);

    const int tid  = threadIdx.x;
    const int wid  = tid >> 5;
    const int lane = tid & 31;
    const int wm   = wid >> 2;
    const int wn   = wid & 3;
    const int b    = blockIdx.y;
    const int m0g  = (blockIdx.x >> 3) * 64;
    const int n0   = (blockIdx.x & 7) * 128;

    const int ar  = tid >> 2;
    const int ac  = (tid & 3) << 3;
    const int br  = tid >> 4;
    const int bc  = (tid & 15) << 3;

    const __nv_bfloat16* AgH = g_Whi + (size_t)(m0g + ar) * 256 + ac;
    const __nv_bfloat16* AgL = g_Wlo + (size_t)(m0g + ar) * 256 + ac;
    const __nv_bfloat16* BgH = g_Xhi + ((size_t)(b * 256 + br)) * 1024 + n0 + bc;
    const __nv_bfloat16* BgL = g_Xlo + ((size_t)(b * 256 + br)) * 1024 + n0 + bc;

    const uint32_t adst = (uint32_t)(ar * SKA + ac) * 2u;
    const uint32_t bdst = (uint32_t)(br * SKB + bc) * 2u;

    auto issue = [&](int ch) {
        const uint32_t stb = sm_base + (ch & 1) * STG_BYTES;
        const int k0 = ch * 32;
        CP_ASYNC16(stb + adst,          AgH + k0);
        CP_ASYNC16(stb + OFF_AL + adst, AgL + k0);
        #pragma unroll
        for (int t = 0; t < 2; t++) {
            uint32_t d = bdst + (uint32_t)(t * 16 * SKB) * 2u;
            CP_ASYNC16(stb + OFF_BH + d, BgH + (size_t)(k0 + t * 16) * 1024);
            CP_ASYNC16(stb + OFF_BL + d, BgL + (size_t)(k0 + t * 16) * 1024);
        }
        CP_COMMIT();
    };

    issue(0);
    issue(1);

    float acc[2][4][4];
    #pragma unroll
    for (int i = 0; i < 2; i++)
        #pragma unroll
        for (int j = 0; j < 4; j++)
            #pragma unroll
            for (int r = 0; r < 4; r++) acc[i][j][r] = 0.f;

    #pragma unroll
    for (int ch = 0; ch < 8; ch++) {
        if (ch < 7) { CP_WAIT(1); } else { CP_WAIT(0); }
        __syncthreads();

        const uint32_t stb = sm_base + (ch & 1) * STG_BYTES;
        #pragma unroll
        for (int ks = 0; ks < 2; ks++) {
            const int kk = ks * 16;
            uint32_t afh[2][4], afl[2][4];
            #pragma unroll
            for (int mt = 0; mt < 2; mt++) {
                uint32_t aoff = (uint32_t)((wm * 32 + mt * 16 + (lane & 15)) * SKA
                                           + kk + ((lane >> 4) << 3)) * 2u;
                ldsm_x4(afh[mt], stb + aoff);
                ldsm_x4(afl[mt], stb + OFF_AL + aoff);
            }
            uint32_t bfh[4][2], bfl[4][2];
            #pragma unroll
            for (int p = 0; p < 2; p++) {
                uint32_t boff = (uint32_t)((kk + (lane & 15)) * SKB
                                           + wn * 32 + p * 16 + ((lane >> 4) << 3)) * 2u;
                uint32_t r[4];
                ldsm_x4_t(r, stb + OFF_BH + boff);
                bfh[p * 2][0] = r[0]; bfh[p * 2][1] = r[1];
                bfh[p * 2 + 1][0] = r[2]; bfh[p * 2 + 1][1] = r[3];
                ldsm_x4_t(r, stb + OFF_BL + boff);
                bfl[p * 2][0] = r[0]; bfl[p * 2][1] = r[1];
                bfl[p * 2 + 1][0] = r[2]; bfl[p * 2 + 1][1] = r[3];
            }
            #pragma unroll
            for (int mt = 0; mt < 2; mt++)
                #pragma unroll
                for (int nt = 0; nt < 4; nt++) {
                    mma_bf16(acc[mt][nt], afh[mt], bfh[nt][0], bfh[nt][1]);
                    mma_bf16(acc[mt][nt], afh[mt], bfl[nt][0], bfl[nt][1]);
                    mma_bf16(acc[mt][nt], afl[mt], bfh[nt][0], bfh[nt][1]);
                }
        }
        __syncthreads();
        if (ch + 2 < 8) issue(ch + 2);
    }

    const int mat = m0g >> 8;
    float* outp = (mat == 0) ? g_q : (mat == 1) ? g_k : g_v;
    const int orow = (m0g & 255) + wm * 32;
    #pragma unroll
    for (int mt = 0; mt < 2; mt++) {
        int o = orow + mt * 16 + (lane >> 2);
        #pragma unroll
        for (int nt = 0; nt < 4; nt++) {
            int n = n0 + wn * 32 + nt * 8 + ((lane & 3) << 1);
            float* og = outp + ((size_t)(b * CC + o)) * HWN + n;
            *(float2*)og = make_float2(acc[mt][nt][0], acc[mt][nt][1]);
            *(float2*)(og + 8 * HWN) = make_float2(acc[mt][nt][2], acc[mt][nt][3]);
        }
    }
}

// ---------------------------------------------------------------------------
// Windowed softmax attention: persistent blocks with atomic plane-stealing.
// grid 592 (= 4 x 148, every SM full); 1024 plane work-units total.
// ---------------------------------------------------------------------------
__global__ __launch_bounds__(256) void attn_kernel(
    const float* __restrict__ rel_h,
    const float* __restrict__ rel_w,
    float* __restrict__ out)
{
    __shared__ __align__(16) float ks[PHW2];
    __shared__ __align__(16) float vs[PHW2];
    __shared__ float brow_s[8];
    __shared__ int s_p;

    const int tid = threadIdx.x;
    const int p0 = tid * 4;
    const int h  = p0 >> 5;
    const int w0 = p0 & 31;
    const int pi0 = (h + 3) * PW2 + (w0 + 4);

    // zero once; borders stay zero, interior overwritten per plane
    {
        const float4 z = make_float4(0.f, 0.f, 0.f, 0.f);
        for (int i = tid; i < PHW2 / 4; i += 256) {
            ((float4*)ks)[i] = z;
            ((float4*)vs)[i] = z;
        }
    }

    const uint32_t ksa = smem_u32(ks) + pi0 * 4;
    const uint32_t vsa = smem_u32(vs) + pi0 * 4;
    const float LOG2E = 1.4426950408889634f;

    for (;;) {
        __syncthreads();                 // prior compute done (and zeroing, first pass)
        if (tid == 0) s_p = atomicAdd(&g_attn_ctr, 1);
        __syncthreads();
        const int p = s_p;
        if (p >= BB * CC) break;

        const int c = p & 255;
        const bool hsel = (c < CC / 2);

        if (tid < KW)
            brow_s[tid] = hsel ? rel_h[c * KW + tid] : rel_w[(c - CC / 2) * KW + tid];

        CP_ASYNC16(ksa, g_k + ((size_t)p) * HWN + p0);
        CP_ASYNC16(vsa, g_v + ((size_t)p) * HWN + p0);
        CP_COMMIT();

        float4 qv = *(const float4*)(g_q + ((size_t)p) * HWN + p0);

        CP_WAIT(0);
        __syncthreads();

        float q2[4] = { qv.x * LOG2E, qv.y * LOG2E, qv.z * LOG2E, qv.w * LOG2E };
        float acc[4] = {0.f, 0.f, 0.f, 0.f};
        float sum[4] = {0.f, 0.f, 0.f, 0.f};

        if (hsel) {
            #pragma unroll
            for (int u = 0; u < KW; u++) {
                const int rbase = (h + u) * PW2 + w0 + 1;
                float kr[10], vr[10];
                #pragma unroll
                for (int i = 0; i < 10; i++) { kr[i] = ks[rbase + i]; vr[i] = vs[rbase + i]; }
                const float bu = brow_s[u];
                float qbu[4];
                #pragma unroll
                for (int jj = 0; jj < 4; jj++) qbu[jj] = q2[jj] * bu;
                #pragma unroll
                for (int v = 0; v < KW; v++) {
                    #pragma unroll
                    for (int jj = 0; jj < 4; jj++) {
                        float t = fmaf(q2[jj], kr[v + jj], qbu[jj]);
                        float e = ex2f(t);
                        sum[jj] += e;
                        acc[jj]  = fmaf(e, vr[v + jj], acc[jj]);
                    }
                }
            }
        } else {
            float qb[4][KW];
            #pragma unroll
            for (int jj = 0; jj < 4; jj++)
                #pragma unroll
                for (int i = 0; i < KW; i++)
                    qb[jj][i] = q2[jj] * brow_s[i];
            #pragma unroll
            for (int u = 0; u < KW; u++) {
                const int rbase = (h + u) * PW2 + w0 + 1;
                float kr[10], vr[10];
                #pragma unroll
                for (int i = 0; i < 10; i++) { kr[i] = ks[rbase + i]; vr[i] = vs[rbase + i]; }
                #pragma unroll
                for (int v = 0; v < KW; v++) {
                    #pragma unroll
                    for (int jj = 0; jj < 4; jj++) {
                        float t = fmaf(q2[jj], kr[v + jj], qb[jj][v]);
                        float e = ex2f(t);
                        sum[jj] += e;
                        acc[jj]  = fmaf(e, vr[v + jj], acc[jj]);
                    }
                }
            }
        }

        float* og = out + ((size_t)p) * HWN + p0;
        float4 r;
        r.x = __fdividef(acc[0], sum[0]);
        r.y = __fdividef(acc[1], sum[1]);
        r.z = __fdividef(acc[2], sum[2]);
        r.w = __fdividef(acc[3], sum[3]);
        *(float4*)og = r;
    }
}

// ---------------------------------------------------------------------------
extern "C" void kernel_launch(void* const* d_in, const int* in_sizes, int n_in,
                              void* d_out, int out_size)
{
    const float* x     = (const float*)d_in[0];
    const float* wq    = (const float*)d_in[1];
    const float* wk    = (const float*)d_in[2];
    const float* wv    = (const float*)d_in[3];
    const float* rel_h = (const float*)d_in[4];
    const float* rel_w = (const float*)d_in[5];
    float* out = (float*)d_out;

    cudaFuncSetAttribute(qkv_mma_kernel, cudaFuncAttributeMaxDynamicSharedMemorySize,
                         SMEM_TOTAL);

    convert_kernel<<<1216, 256>>>(x, wq, wk, wv);

    dim3 gg(96, BB);
    qkv_mma_kernel<<<gg, 256, SMEM_TOTAL>>>();

    attn_kernel<<<592, 256>>>(rel_h, rel_w, out);
}